// round 1
// baseline (speedup 1.0000x reference)
#include <cuda_runtime.h>
#include <cstdint>

// Problem constants (from reference: feats [16,256,128,128], queue [256,256],
// labels [262144,256], TEMPERATURE = 0.07)
#define C_DIM   256
#define M_DIM   256
#define HW_DIM  16384          // 128*128
#define NPIX    262144         // 16*128*128
#define P_TILE  32             // pixels per block
#define KC      32             // K chunk through smem
#define NCHUNK  (C_DIM / KC)   // 8
#define GRID_N  (NPIX / P_TILE) // 8192
#define INV_T   14.285714285714285f  // 1/0.07

// Deterministic reduction scratch (no cudaMalloc allowed)
__device__ float g_partial[GRID_N];
__device__ int   g_pcnt[GRID_N];

__global__ void __launch_bounds__(256)
pcl_main_kernel(const float* __restrict__ feats,
                const float* __restrict__ queue,
                const int*   __restrict__ labels)
{
    // smem: queue chunk padded to 36 floats/row (16B-aligned float4 rows,
    // conflict-free per-thread-class column reads), feats chunk [k][p].
    __shared__ __align__(16) float sq[M_DIM][36];
    __shared__ __align__(16) float fs[KC][P_TILE];
    __shared__ float red_n[P_TILE][8];
    __shared__ float red_p[P_TILE][8];

    const int t    = threadIdx.x;     // 0..255, owns class j = t
    const int lane = t & 31;
    const int wid  = t >> 5;
    const int n0   = blockIdx.x * P_TILE;
    const int b    = n0 / HW_DIM;
    const int hw0  = n0 % HW_DIM;     // P_TILE divides HW_DIM: never crosses batch
    const size_t fbase = (size_t)b * C_DIM * HW_DIM + hw0;

    float acc[P_TILE];
#pragma unroll
    for (int p = 0; p < P_TILE; p++) acc[p] = 0.0f;

    for (int ch = 0; ch < NCHUNK; ch++) {
        const int k0 = ch * KC;
        __syncthreads();
        // queue chunk: warp w loads contiguous 128B of row (wid + it*8)
#pragma unroll
        for (int it = 0; it < M_DIM / 8; it++) {
            int row = wid + it * 8;
            sq[row][lane] = queue[row * C_DIM + k0 + lane];
        }
        // feats chunk: warp w loads 32 contiguous pixels of channel (k0 + wid + it*8)
#pragma unroll
        for (int it = 0; it < KC / 8; it++) {
            int k = wid + it * 8;
            fs[k][lane] = feats[fbase + (size_t)(k0 + k) * HW_DIM + lane];
        }
        __syncthreads();

        // FFMA core: per k, 32 FFMA + 8 broadcast LDS.128 per thread
#pragma unroll 1
        for (int k4 = 0; k4 < KC; k4 += 4) {
            float4 q4 = *(const float4*)&sq[t][k4];
            const float4* f0 = (const float4*)&fs[k4 + 0][0];
            const float4* f1 = (const float4*)&fs[k4 + 1][0];
            const float4* f2 = (const float4*)&fs[k4 + 2][0];
            const float4* f3 = (const float4*)&fs[k4 + 3][0];
#pragma unroll
            for (int pg = 0; pg < P_TILE / 4; pg++) {
                float4 fa = f0[pg];
                acc[4*pg+0] += fa.x * q4.x; acc[4*pg+1] += fa.y * q4.x;
                acc[4*pg+2] += fa.z * q4.x; acc[4*pg+3] += fa.w * q4.x;
                float4 fb = f1[pg];
                acc[4*pg+0] += fb.x * q4.y; acc[4*pg+1] += fb.y * q4.y;
                acc[4*pg+2] += fb.z * q4.y; acc[4*pg+3] += fb.w * q4.y;
                float4 fc = f2[pg];
                acc[4*pg+0] += fc.x * q4.z; acc[4*pg+1] += fc.y * q4.z;
                acc[4*pg+2] += fc.z * q4.z; acc[4*pg+3] += fc.w * q4.z;
                float4 fd = f3[pg];
                acc[4*pg+0] += fd.x * q4.w; acc[4*pg+1] += fd.y * q4.w;
                acc[4*pg+2] += fd.z * q4.w; acc[4*pg+3] += fd.w * q4.w;
            }
        }
    }

    // Epilogue: per pixel p, sum_neg = sum_j (1-y)exp(l), sum_pos = sum_j y*exp(-l)
#pragma unroll 1
    for (int p = 0; p < P_TILE; p++) {
        int   y  = labels[((size_t)(n0 + p) << 8) + t];  // coalesced across classes
        float l  = acc[p] * INV_T;
        float en = y ? 0.0f : __expf(l);
        float ep = y ? __expf(-l) : 0.0f;
#pragma unroll
        for (int off = 16; off > 0; off >>= 1) {
            en += __shfl_xor_sync(0xffffffffu, en, off);
            ep += __shfl_xor_sync(0xffffffffu, ep, off);
        }
        if (lane == 0) { red_n[p][wid] = en; red_p[p][wid] = ep; }
    }
    __syncthreads();

    if (t < P_TILE) {  // warp 0: one pixel per lane
        float sn = 0.0f, sp = 0.0f;
#pragma unroll
        for (int w = 0; w < 8; w++) { sn += red_n[t][w]; sp += red_p[t][w]; }
        float loss = __logf(sn * sp + 1.0f);
        float ls = loss;
        int   c  = (loss != 0.0f) ? 1 : 0;
#pragma unroll
        for (int off = 16; off > 0; off >>= 1) {
            ls += __shfl_xor_sync(0xffffffffu, ls, off);
            c  += __shfl_xor_sync(0xffffffffu, c,  off);
        }
        if (t == 0) { g_partial[blockIdx.x] = ls; g_pcnt[blockIdx.x] = c; }
    }
}

__global__ void pcl_finalize_kernel(float* __restrict__ out)
{
    __shared__ float ss[256];
    __shared__ int   sc[256];
    float s = 0.0f; int c = 0;
    for (int i = threadIdx.x; i < GRID_N; i += 256) {
        s += g_partial[i];
        c += g_pcnt[i];
    }
    ss[threadIdx.x] = s; sc[threadIdx.x] = c;
    __syncthreads();
    for (int off = 128; off > 0; off >>= 1) {
        if (threadIdx.x < off) {
            ss[threadIdx.x] += ss[threadIdx.x + off];
            sc[threadIdx.x] += sc[threadIdx.x + off];
        }
        __syncthreads();
    }
    if (threadIdx.x == 0) {
        int cnt = sc[0];
        out[0] = (cnt == 0) ? 0.0f : ss[0] / (float)(cnt < 1 ? 1 : cnt);
    }
}

extern "C" void kernel_launch(void* const* d_in, const int* in_sizes, int n_in,
                              void* d_out, int out_size)
{
    const float* feats  = (const float*)d_in[0];
    const float* queue  = (const float*)d_in[1];
    const int*   labels = (const int*)d_in[2];
    float* out = (float*)d_out;

    pcl_main_kernel<<<GRID_N, 256>>>(feats, queue, labels);
    pcl_finalize_kernel<<<1, 256>>>(out);
}

// round 3
// speedup vs baseline: 5.4952x; 5.4952x over previous
#include <cuda_runtime.h>
#include <cuda_bf16.h>
#include <cstdint>

#define NPIX   262144
#define CD     256
#define HW     16384
#define TILE_P 128
#define NBLK   (NPIX / TILE_P)      // 2048
#define INV_T  14.285714285714285f

// smem layout (bytes). Padded strides keep ldmatrix reads conflict-free:
//  B (queue bf16 [256 n][256 k]): stride 528  (132 words -> 4r mod 32 banks)
//  A^T (feats bf16 [256 k][128 m]): stride 272 (68 words  -> 4r mod 32 banks)
#define B_STRIDE 528
#define A_STRIDE 272
#define OFF_B    0
#define OFF_A    (256 * B_STRIDE)                 // 135168
#define OFF_LAB  (OFF_A + 256 * A_STRIDE)         // 204800  (128 px * 8 words)
#define OFF_RED  (OFF_LAB + 128 * 8 * 4)          // 208896  s_en[128][4], s_ep[128][4]
#define OFF_RED2 (OFF_RED + 128 * 4 * 4 * 2)      // 212992  block-reduce scratch
#define SMEM_SZ  (OFF_RED2 + 256)                 // ~213.2 KB

__device__ float g_partial[NBLK];
__device__ int   g_pcnt[NBLK];

__device__ __forceinline__ uint32_t smem_u32(const void* p) {
    uint32_t a;
    asm("{ .reg .u64 t; cvta.to.shared.u64 t, %1; cvt.u32.u64 %0, t; }" : "=r"(a) : "l"(p));
    return a;
}

__device__ __forceinline__ void ldsm_x4(uint32_t* r, uint32_t addr) {
    asm volatile("ldmatrix.sync.aligned.m8n8.x4.shared.b16 {%0,%1,%2,%3}, [%4];"
                 : "=r"(r[0]), "=r"(r[1]), "=r"(r[2]), "=r"(r[3]) : "r"(addr));
}
__device__ __forceinline__ void ldsm_x4_t(uint32_t* r, uint32_t addr) {
    asm volatile("ldmatrix.sync.aligned.m8n8.x4.trans.shared.b16 {%0,%1,%2,%3}, [%4];"
                 : "=r"(r[0]), "=r"(r[1]), "=r"(r[2]), "=r"(r[3]) : "r"(addr));
}
__device__ __forceinline__ void mma_bf16(float* d, const uint32_t* a,
                                         uint32_t b0, uint32_t b1) {
    asm volatile(
        "mma.sync.aligned.m16n8k16.row.col.f32.bf16.bf16.f32 "
        "{%0,%1,%2,%3}, {%4,%5,%6,%7}, {%8,%9}, {%0,%1,%2,%3};"
        : "+f"(d[0]), "+f"(d[1]), "+f"(d[2]), "+f"(d[3])
        : "r"(a[0]), "r"(a[1]), "r"(a[2]), "r"(a[3]), "r"(b0), "r"(b1));
}

// ===================== fused main kernel =====================
// Block: 256 thr (8 warps, 2x4 warp grid). Tile: 128 pixels x 256 classes, K=256.
__global__ void __launch_bounds__(256, 1)
pcl_main(const float* __restrict__ feats, const float* __restrict__ queue,
         const int* __restrict__ labels)
{
    extern __shared__ char smem[];
    const int tid = threadIdx.x, lane = tid & 31, wid = tid >> 5;
    const int wm = wid >> 2, wn = wid & 3;
    const int n0 = blockIdx.x * TILE_P;
    const int b = n0 / HW, hw0 = n0 % HW;
    const float* fbase = feats + (size_t)b * CD * HW + hw0;

    // ---- stage B: queue fp32 -> bf16 [n][k] (coalesced float2 reads) ----
    for (int i = tid; i < 256 * 128; i += 256) {
        int n = i >> 7, k2 = i & 127;
        float2 v = *(const float2*)(queue + n * 256 + k2 * 2);
        *(__nv_bfloat162*)(smem + OFF_B + n * B_STRIDE + k2 * 4) =
            __floats2bfloat162_rn(v.x, v.y);
    }
    // ---- stage A^T: feats fp32 [c][hw] -> bf16 [k][m] (coalesced, no transpose cost) ----
    for (int i = tid; i < 256 * 64; i += 256) {
        int c = i >> 6, jp = i & 63;
        float2 v = *(const float2*)(fbase + (size_t)c * HW + jp * 2);
        *(__nv_bfloat162*)(smem + OFF_A + c * A_STRIDE + jp * 4) =
            __floats2bfloat162_rn(v.x, v.y);
    }
    // ---- pack labels into bitmasks (coalesced LDG + ballot) ----
    unsigned* labm = (unsigned*)(smem + OFF_LAB);
    for (int p = wid * 16; p < wid * 16 + 16; p++) {
        const int* lp = labels + (size_t)(n0 + p) * 256;
#pragma unroll
        for (int cw = 0; cw < 8; cw++) {
            unsigned m = __ballot_sync(0xffffffffu, lp[cw * 32 + lane] != 0);
            if (lane == 0) labm[p * 8 + cw] = m;
        }
    }
    __syncthreads();

    // ---- GEMM: warp tile 64x64, m16n8k16 ----
    const uint32_t sb = smem_u32(smem);
    const int r8   = lane & 7;
    const int sel8 = (lane >> 3) & 1;   // +8 in m (A) / n (B)
    const int selk = (lane >> 4) & 1;   // +8 in k

    float acc[4][8][4];
#pragma unroll
    for (int mb = 0; mb < 4; mb++)
#pragma unroll
        for (int nb = 0; nb < 8; nb++)
#pragma unroll
            for (int e = 0; e < 4; e++) acc[mb][nb][e] = 0.0f;

    // lane-invariant-per-thread address bases
    uint32_t a_base = sb + OFF_A + (uint32_t)(selk * 8 + r8) * A_STRIDE
                      + (uint32_t)(wm * 64 + sel8 * 8) * 2;
    uint32_t b_base = sb + OFF_B + (uint32_t)(wn * 64 + sel8 * 8 + r8) * B_STRIDE
                      + (uint32_t)(selk * 8) * 2;

#pragma unroll 1
    for (int ks = 0; ks < 16; ks++) {
        uint32_t a[4][4], bq[4][4];
#pragma unroll
        for (int mb = 0; mb < 4; mb++)
            ldsm_x4_t(a[mb], a_base + (uint32_t)ks * 16 * A_STRIDE + mb * 16 * 2);
#pragma unroll
        for (int nbp = 0; nbp < 4; nbp++)
            ldsm_x4(bq[nbp], b_base + (uint32_t)nbp * 16 * B_STRIDE + ks * 16 * 2);
#pragma unroll
        for (int mb = 0; mb < 4; mb++)
#pragma unroll
            for (int nbp = 0; nbp < 4; nbp++) {
                mma_bf16(acc[mb][2 * nbp],     a[mb], bq[nbp][0], bq[nbp][2]);
                mma_bf16(acc[mb][2 * nbp + 1], a[mb], bq[nbp][1], bq[nbp][3]);
            }
    }

    // ---- epilogue: thread-local masked exp sums, quad reduce, cross-warp via smem ----
    float* s_en = (float*)(smem + OFF_RED);   // [128][4]
    float* s_ep = s_en + 512;
#pragma unroll
    for (int mb = 0; mb < 4; mb++) {
#pragma unroll
        for (int half = 0; half < 2; half++) {
            int row = wm * 64 + mb * 16 + (lane >> 2) + half * 8;  // pixel in tile
            unsigned mw0 = labm[row * 8 + wn * 2];
            unsigned mw1 = labm[row * 8 + wn * 2 + 1];
            float en = 0.0f, ep = 0.0f;
#pragma unroll
            for (int nb = 0; nb < 8; nb++) {
                unsigned mw = (nb < 4) ? mw0 : mw1;
                int bit0 = (nb & 3) * 8 + (lane & 3) * 2;
                float l0 = acc[mb][nb][half * 2]     * INV_T;
                float l1 = acc[mb][nb][half * 2 + 1] * INV_T;
                bool y0 = (mw >> bit0) & 1u;
                bool y1 = (mw >> (bit0 + 1)) & 1u;
                float e0 = __expf(y0 ? -l0 : l0);
                float e1 = __expf(y1 ? -l1 : l1);
                en += y0 ? 0.0f : e0;  ep += y0 ? e0 : 0.0f;
                en += y1 ? 0.0f : e1;  ep += y1 ? e1 : 0.0f;
            }
            en += __shfl_xor_sync(0xffffffffu, en, 1);
            en += __shfl_xor_sync(0xffffffffu, en, 2);
            ep += __shfl_xor_sync(0xffffffffu, ep, 1);
            ep += __shfl_xor_sync(0xffffffffu, ep, 2);
            if ((lane & 3) == 0) { s_en[row * 4 + wn] = en; s_ep[row * 4 + wn] = ep; }
        }
    }
    __syncthreads();

    float lsum = 0.0f; int lcnt = 0;
    if (tid < 128) {
        float en = s_en[tid * 4] + s_en[tid * 4 + 1] + s_en[tid * 4 + 2] + s_en[tid * 4 + 3];
        float ep = s_ep[tid * 4] + s_ep[tid * 4 + 1] + s_ep[tid * 4 + 2] + s_ep[tid * 4 + 3];
        float loss = __logf(en * ep + 1.0f);
        lsum = loss;
        lcnt = (loss != 0.0f) ? 1 : 0;
    }
#pragma unroll
    for (int off = 16; off > 0; off >>= 1) {
        lsum += __shfl_xor_sync(0xffffffffu, lsum, off);
        lcnt += __shfl_xor_sync(0xffffffffu, lcnt, off);
    }
    float* redf = (float*)(smem + OFF_RED2);
    int*   redi = (int*)(smem + OFF_RED2 + 64);
    if (lane == 0) { redf[wid] = lsum; redi[wid] = lcnt; }
    __syncthreads();
    if (tid == 0) {
        float s = 0.0f; int c = 0;
#pragma unroll
        for (int w = 0; w < 8; w++) { s += redf[w]; c += redi[w]; }
        g_partial[blockIdx.x] = s;
        g_pcnt[blockIdx.x]    = c;
    }
}

// ===================== finalize =====================
__global__ void __launch_bounds__(256) pcl_finalize(float* __restrict__ out)
{
    __shared__ float ss[256];
    __shared__ int   sc[256];
    float s = 0.0f; int c = 0;
    for (int i = threadIdx.x; i < NBLK; i += 256) { s += g_partial[i]; c += g_pcnt[i]; }
    ss[threadIdx.x] = s; sc[threadIdx.x] = c;
    __syncthreads();
    for (int off = 128; off > 0; off >>= 1) {
        if (threadIdx.x < off) {
            ss[threadIdx.x] += ss[threadIdx.x + off];
            sc[threadIdx.x] += sc[threadIdx.x + off];
        }
        __syncthreads();
    }
    if (threadIdx.x == 0) {
        int cnt = sc[0];
        out[0] = (cnt == 0) ? 0.0f : ss[0] / (float)(cnt < 1 ? 1 : cnt);
    }
}

extern "C" void kernel_launch(void* const* d_in, const int* in_sizes, int n_in,
                              void* d_out, int out_size)
{
    const float* feats  = (const float*)d_in[0];
    const float* queue  = (const float*)d_in[1];
    const int*   labels = (const int*)d_in[2];
    float* out = (float*)d_out;

    static bool attr_set = false;
    if (!attr_set) {
        cudaFuncSetAttribute(pcl_main,
                             cudaFuncAttributeMaxDynamicSharedMemorySize, SMEM_SZ);
        attr_set = true;
    }

    pcl_main<<<NBLK, 256, SMEM_SZ>>>(feats, queue, labels);
    pcl_finalize<<<1, 256>>>(out);
}

// round 4
// speedup vs baseline: 8.4147x; 1.5313x over previous
#include <cuda_runtime.h>
#include <cuda_bf16.h>
#include <cstdint>

#define NPIX   262144
#define CD     256
#define HW     16384
#define TILE_P 64
#define TILES  8
#define BLK_PX (TILE_P * TILES)     // 512 pixels per block
#define NBLK   (NPIX / BLK_PX)      // 512 blocks
#define INV_T  14.285714285714285f

// smem layout (bytes)
#define B_STRIDE 528                 // 256 bf16 + pad: conflict-free ldsm
#define A_STRIDE 144                 // 64 bf16 + pad:  conflict-free ldsm.trans
#define A_BUF    (256 * A_STRIDE)    // 36864
#define OFF_B    0
#define OFF_A    (256 * B_STRIDE)    // 135168
#define OFF_LAB  (OFF_A + 2 * A_BUF) // 208896 : 2 x (64 px * 16 u16)
#define OFF_RED  (OFF_LAB + 2 * 2048)// 212992 : s_en[64][4], s_ep[64][4]
#define OFF_RED2 (OFF_RED + 2048)    // 215040
#define SMEM_SZ  (OFF_RED2 + 256)    // 215296

__device__ float g_partial[NBLK];
__device__ int   g_pcnt[NBLK];

__device__ __forceinline__ uint32_t smem_u32(const void* p) {
    uint32_t a;
    asm("{ .reg .u64 t; cvta.to.shared.u64 t, %1; cvt.u32.u64 %0, t; }" : "=r"(a) : "l"(p));
    return a;
}
__device__ __forceinline__ void ldsm_x4(uint32_t* r, uint32_t addr) {
    asm volatile("ldmatrix.sync.aligned.m8n8.x4.shared.b16 {%0,%1,%2,%3}, [%4];"
                 : "=r"(r[0]), "=r"(r[1]), "=r"(r[2]), "=r"(r[3]) : "r"(addr));
}
__device__ __forceinline__ void ldsm_x4_t(uint32_t* r, uint32_t addr) {
    asm volatile("ldmatrix.sync.aligned.m8n8.x4.trans.shared.b16 {%0,%1,%2,%3}, [%4];"
                 : "=r"(r[0]), "=r"(r[1]), "=r"(r[2]), "=r"(r[3]) : "r"(addr));
}
__device__ __forceinline__ void mma_bf16(float* d, const uint32_t* a,
                                         uint32_t b0, uint32_t b1) {
    asm volatile(
        "mma.sync.aligned.m16n8k16.row.col.f32.bf16.bf16.f32 "
        "{%0,%1,%2,%3}, {%4,%5,%6,%7}, {%8,%9}, {%0,%1,%2,%3};"
        : "+f"(d[0]), "+f"(d[1]), "+f"(d[2]), "+f"(d[3])
        : "r"(a[0]), "r"(a[1]), "r"(a[2]), "r"(a[3]), "r"(b0), "r"(b1));
}

// ===================== fused pipelined main kernel =====================
// 256 thr (8 warps: wm 0..1 x wn 0..3). Block: 512 px in 8 tiles of 64.
// Queue resident in smem. A+labels for tile t+1 streamed inside tile t's mma loop.
__global__ void __launch_bounds__(256, 1)
pcl_main(const float* __restrict__ feats, const float* __restrict__ queue,
         const int* __restrict__ labels)
{
    extern __shared__ char smem[];
    const uint32_t sb = smem_u32(smem);
    const int tid = threadIdx.x, lane = tid & 31, wid = tid >> 5;
    const int wm = wid >> 2, wn = wid & 3;
    const int base = blockIdx.x * BLK_PX;
    const int b = base / HW, hw0 = base % HW;
    const float* fbase = feats + (size_t)b * CD * HW + hw0;

    // ---- stage B once: queue fp32 -> bf16 [n][k] ----
    for (int i = tid; i < 256 * 128; i += 256) {
        int n = i >> 7, k2 = i & 127;
        float2 v = *(const float2*)(queue + n * 256 + k2 * 2);
        *(__nv_bfloat162*)(smem + OFF_B + n * B_STRIDE + k2 * 4) =
            __floats2bfloat162_rn(v.x, v.y);
    }
    // ---- stage A tile 0 (buf 0): feats [c][hw] -> bf16 [k][m] ----
    for (int i = tid; i < 256 * 32; i += 256) {
        int row = i >> 5, p2 = i & 31;
        float2 v = *(const float2*)(fbase + (size_t)row * HW + p2 * 2);
        *(__nv_bfloat162*)(smem + OFF_A + row * A_STRIDE + p2 * 4) =
            __floats2bfloat162_rn(v.x, v.y);
    }
    // ---- stage labels tile 0 (buf 0): 16-bit masks ----
    for (int s = tid; s < 1024; s += 256) {
        int px = s >> 4, hwi = s & 15;
        const int4* lp = (const int4*)(labels + (size_t)(base + px) * 256 + hwi * 16);
        unsigned m = 0;
#pragma unroll
        for (int j = 0; j < 4; j++) {
            int4 v = lp[j];
            m |= (v.x != 0 ? 1u : 0u) << (j * 4);
            m |= (v.y != 0 ? 1u : 0u) << (j * 4 + 1);
            m |= (v.z != 0 ? 1u : 0u) << (j * 4 + 2);
            m |= (v.w != 0 ? 1u : 0u) << (j * 4 + 3);
        }
        ((unsigned short*)(smem + OFF_LAB))[px * 16 + hwi] = (unsigned short)m;
    }
    __syncthreads();

    // ldsm lane decomposition
    const int r8   = lane & 7;
    const int sel8 = (lane >> 3) & 1;
    const int selk = (lane >> 4) & 1;
    const uint32_t b_base = sb + OFF_B
        + (uint32_t)(wn * 64 + sel8 * 8 + r8) * B_STRIDE + (uint32_t)(selk * 8) * 2;
    const uint32_t a_lane_off =
        (uint32_t)(selk * 8 + r8) * A_STRIDE + (uint32_t)(wm * 32 + sel8 * 8) * 2;

    float lsum = 0.0f; int lcnt = 0;

#pragma unroll 1
    for (int t = 0; t < TILES; t++) {
        const int cur = t & 1, nxt = cur ^ 1;
        const uint32_t a_base = sb + OFF_A + (uint32_t)cur * A_BUF + a_lane_off;
        char* anxt = smem + OFF_A + nxt * A_BUF;
        unsigned short* lmnxt = (unsigned short*)(smem + OFF_LAB + nxt * 2048);
        const bool pf = (t + 1 < TILES);
        // prefetch source pointers (tile t+1)
        const float* fnx = fbase + (t + 1) * TILE_P;
        const int*   lnx = labels + (size_t)(base + (t + 1) * TILE_P) * 256;

        float acc[2][8][4];
#pragma unroll
        for (int mb = 0; mb < 2; mb++)
#pragma unroll
            for (int nb = 0; nb < 8; nb++)
#pragma unroll
                for (int e = 0; e < 4; e++) acc[mb][nb][e] = 0.0f;

#pragma unroll
        for (int g = 0; g < 4; g++) {
            float4 pa[4]; int4 pl[4];
            int rowp = g * 64 + (tid >> 2);
            int slot = g * 256 + tid, pxl = slot >> 4, hwi = slot & 15;
            if (pf) {
                const float4* asrc = (const float4*)(fnx + (size_t)rowp * HW);
                const int4*   lsrc = (const int4*)(lnx + pxl * 256 + hwi * 16);
#pragma unroll
                for (int i = 0; i < 4; i++) pa[i] = asrc[i * 4 + (tid & 3)];
#pragma unroll
                for (int i = 0; i < 4; i++) pl[i] = lsrc[i];
            }
            // 4 ksteps of mma on tile t
#pragma unroll
            for (int kk = 0; kk < 4; kk++) {
                const int ks = g * 4 + kk;
                uint32_t a[2][4], bq[4][4];
#pragma unroll
                for (int mb = 0; mb < 2; mb++)
                    ldsm_x4_t(a[mb], a_base + (uint32_t)ks * 16 * A_STRIDE + mb * 16 * 2);
#pragma unroll
                for (int nbp = 0; nbp < 4; nbp++)
                    ldsm_x4(bq[nbp], b_base + (uint32_t)nbp * 16 * B_STRIDE + ks * 16 * 2);
#pragma unroll
                for (int mb = 0; mb < 2; mb++)
#pragma unroll
                    for (int nbp = 0; nbp < 4; nbp++) {
                        mma_bf16(acc[mb][2 * nbp],     a[mb], bq[nbp][0], bq[nbp][2]);
                        mma_bf16(acc[mb][2 * nbp + 1], a[mb], bq[nbp][1], bq[nbp][3]);
                    }
            }
            // drain prefetch into nxt buffers
            if (pf) {
#pragma unroll
                for (int i = 0; i < 4; i++) {
                    int f4 = i * 4 + (tid & 3);
                    __nv_bfloat162 lo = __floats2bfloat162_rn(pa[i].x, pa[i].y);
                    __nv_bfloat162 hi = __floats2bfloat162_rn(pa[i].z, pa[i].w);
                    uint2 v = { *(uint32_t*)&lo, *(uint32_t*)&hi };
                    *(uint2*)(anxt + rowp * A_STRIDE + f4 * 8) = v;
                }
                unsigned m = 0;
#pragma unroll
                for (int j = 0; j < 4; j++) {
                    int4 v = pl[j];
                    m |= (v.x != 0 ? 1u : 0u) << (j * 4);
                    m |= (v.y != 0 ? 1u : 0u) << (j * 4 + 1);
                    m |= (v.z != 0 ? 1u : 0u) << (j * 4 + 2);
                    m |= (v.w != 0 ? 1u : 0u) << (j * 4 + 3);
                }
                lmnxt[pxl * 16 + hwi] = (unsigned short)m;
            }
        }
        __syncthreads();   // nxt buffers complete; acc final for tile t

        // ---- epilogue tile t ----
        const unsigned* labm = (const unsigned*)(smem + OFF_LAB + cur * 2048);
        float* s_en = (float*)(smem + OFF_RED);
        float* s_ep = s_en + 256;
#pragma unroll
        for (int mb = 0; mb < 2; mb++) {
#pragma unroll
            for (int half = 0; half < 2; half++) {
                int row = wm * 32 + mb * 16 + (lane >> 2) + half * 8;
                unsigned mw0 = labm[row * 8 + wn * 2];
                unsigned mw1 = labm[row * 8 + wn * 2 + 1];
                float en = 0.0f, ep = 0.0f;
#pragma unroll
                for (int nb = 0; nb < 8; nb++) {
                    unsigned mw = (nb < 4) ? mw0 : mw1;
                    int bit0 = (nb & 3) * 8 + (lane & 3) * 2;
                    float l0 = acc[mb][nb][half * 2]     * INV_T;
                    float l1 = acc[mb][nb][half * 2 + 1] * INV_T;
                    bool y0 = (mw >> bit0) & 1u;
                    bool y1 = (mw >> (bit0 + 1)) & 1u;
                    float e0 = __expf(y0 ? -l0 : l0);
                    float e1 = __expf(y1 ? -l1 : l1);
                    en += y0 ? 0.0f : e0;  ep += y0 ? e0 : 0.0f;
                    en += y1 ? 0.0f : e1;  ep += y1 ? e1 : 0.0f;
                }
                en += __shfl_xor_sync(0xffffffffu, en, 1);
                en += __shfl_xor_sync(0xffffffffu, en, 2);
                ep += __shfl_xor_sync(0xffffffffu, ep, 1);
                ep += __shfl_xor_sync(0xffffffffu, ep, 2);
                if ((lane & 3) == 0) { s_en[row * 4 + wn] = en; s_ep[row * 4 + wn] = ep; }
            }
        }
        __syncthreads();
        if (tid < 64) {
            float en = s_en[tid * 4] + s_en[tid * 4 + 1] + s_en[tid * 4 + 2] + s_en[tid * 4 + 3];
            float ep = s_ep[tid * 4] + s_ep[tid * 4 + 1] + s_ep[tid * 4 + 2] + s_ep[tid * 4 + 3];
            float loss = __logf(en * ep + 1.0f);
            lsum += loss;
            lcnt += (loss != 0.0f) ? 1 : 0;
        }
        __syncthreads();   // protect s_en/labm reuse before next tile's writes
    }

    // ---- deterministic block reduce ----
#pragma unroll
    for (int off = 16; off > 0; off >>= 1) {
        lsum += __shfl_xor_sync(0xffffffffu, lsum, off);
        lcnt += __shfl_xor_sync(0xffffffffu, lcnt, off);
    }
    float* redf = (float*)(smem + OFF_RED2);
    int*   redi = (int*)(smem + OFF_RED2 + 64);
    if (lane == 0) { redf[wid] = lsum; redi[wid] = lcnt; }
    __syncthreads();
    if (tid == 0) {
        float s = 0.0f; int c = 0;
#pragma unroll
        for (int w = 0; w < 8; w++) { s += redf[w]; c += redi[w]; }
        g_partial[blockIdx.x] = s;
        g_pcnt[blockIdx.x]    = c;
    }
}

// ===================== finalize =====================
__global__ void __launch_bounds__(256) pcl_finalize(float* __restrict__ out)
{
    __shared__ float ss[256];
    __shared__ int   sc[256];
    float s = 0.0f; int c = 0;
    for (int i = threadIdx.x; i < NBLK; i += 256) { s += g_partial[i]; c += g_pcnt[i]; }
    ss[threadIdx.x] = s; sc[threadIdx.x] = c;
    __syncthreads();
    for (int off = 128; off > 0; off >>= 1) {
        if (threadIdx.x < off) {
            ss[threadIdx.x] += ss[threadIdx.x + off];
            sc[threadIdx.x] += sc[threadIdx.x + off];
        }
        __syncthreads();
    }
    if (threadIdx.x == 0) {
        int cnt = sc[0];
        out[0] = (cnt == 0) ? 0.0f : ss[0] / (float)(cnt < 1 ? 1 : cnt);
    }
}

extern "C" void kernel_launch(void* const* d_in, const int* in_sizes, int n_in,
                              void* d_out, int out_size)
{
    const float* feats  = (const float*)d_in[0];
    const float* queue  = (const float*)d_in[1];
    const int*   labels = (const int*)d_in[2];
    float* out = (float*)d_out;

    static bool attr_set = false;
    if (!attr_set) {
        cudaFuncSetAttribute(pcl_main,
                             cudaFuncAttributeMaxDynamicSharedMemorySize, SMEM_SZ);
        attr_set = true;
    }

    pcl_main<<<NBLK, 256, SMEM_SZ>>>(feats, queue, labels);
    pcl_finalize<<<1, 256>>>(out);
}

// round 5
// speedup vs baseline: 11.9860x; 1.4244x over previous
#include <cuda_runtime.h>
#include <cuda_bf16.h>
#include <cstdint>

#define NPIX   262144
#define CD     256
#define HW     16384
#define TILE_P 64
#define NTILES (NPIX / TILE_P)      // 4096
#define GRID   148
#define INV_T  14.285714285714285f

// smem layout (bytes)
#define B_STRIDE 528                  // 132 words = 4 mod 32 banks: conflict-free ldsm
#define A_STRIDE 144                  // 36 words  = 4 mod 32 banks
#define A_BUF    (256 * A_STRIDE)     // 36864
#define OFF_B    0
#define OFF_A    (256 * B_STRIDE)     // 135168
#define OFF_LAB  (OFF_A + 2 * A_BUF)  // 208896 : 2 x (64 px * 32 bytes)
#define OFF_RED  (OFF_LAB + 2 * 2048) // 212992 : s_en[64][4], s_ep[64][4]
#define OFF_CTL  (OFF_RED + 2048)     // 215040 : s_next[2]
#define SMEM_SZ  (OFF_CTL + 64)

__device__ float    g_partial[NTILES * 2];
__device__ int      g_pcnt[NTILES * 2];
__device__ unsigned g_counter;

__device__ __forceinline__ uint32_t smem_u32(const void* p) {
    uint32_t a;
    asm("{ .reg .u64 t; cvta.to.shared.u64 t, %1; cvt.u32.u64 %0, t; }" : "=r"(a) : "l"(p));
    return a;
}
__device__ __forceinline__ void ldsm_x4(uint32_t* r, uint32_t addr) {
    asm volatile("ldmatrix.sync.aligned.m8n8.x4.shared.b16 {%0,%1,%2,%3}, [%4];"
                 : "=r"(r[0]), "=r"(r[1]), "=r"(r[2]), "=r"(r[3]) : "r"(addr));
}
__device__ __forceinline__ void ldsm_x4_t(uint32_t* r, uint32_t addr) {
    asm volatile("ldmatrix.sync.aligned.m8n8.x4.trans.shared.b16 {%0,%1,%2,%3}, [%4];"
                 : "=r"(r[0]), "=r"(r[1]), "=r"(r[2]), "=r"(r[3]) : "r"(addr));
}
__device__ __forceinline__ void mma_bf16(float* d, const uint32_t* a,
                                         uint32_t b0, uint32_t b1) {
    asm volatile(
        "mma.sync.aligned.m16n8k16.row.col.f32.bf16.bf16.f32 "
        "{%0,%1,%2,%3}, {%4,%5,%6,%7}, {%8,%9}, {%0,%1,%2,%3};"
        : "+f"(d[0]), "+f"(d[1]), "+f"(d[2]), "+f"(d[3])
        : "r"(a[0]), "r"(a[1]), "r"(a[2]), "r"(a[3]), "r"(b0), "r"(b1));
}
__device__ __forceinline__ unsigned mask8(const int4& v0, const int4& v1) {
    unsigned m = 0;
    m |= (v0.x != 0 ? 1u : 0u);
    m |= (v0.y != 0 ? 2u : 0u);
    m |= (v0.z != 0 ? 4u : 0u);
    m |= (v0.w != 0 ? 8u : 0u);
    m |= (v1.x != 0 ? 16u : 0u);
    m |= (v1.y != 0 ? 32u : 0u);
    m |= (v1.z != 0 ? 64u : 0u);
    m |= (v1.w != 0 ? 128u : 0u);
    return m;
}

__global__ void __launch_bounds__(1) pcl_init() { g_counter = GRID; }

// ===================== persistent fused main kernel =====================
// 148 CTAs x 512 thr (16 warps: wm 0..3 x wn 0..3). Work-steal 4096 tiles of 64 px.
__global__ void __launch_bounds__(512, 1)
pcl_main(const float* __restrict__ feats, const float* __restrict__ queue,
         const int* __restrict__ labels)
{
    extern __shared__ char smem[];
    const uint32_t sb = smem_u32(smem);
    const int tid = threadIdx.x, lane = tid & 31, wid = tid >> 5;
    const int wm = wid >> 2, wn = wid & 3;
    unsigned* s_next = (unsigned*)(smem + OFF_CTL);

    // ---- stage B once: queue fp32 -> bf16 [n][k] ----
    for (int i = tid; i < 256 * 128; i += 512) {
        int n = i >> 7, k2 = i & 127;
        float2 v = *(const float2*)(queue + n * 256 + k2 * 2);
        *(__nv_bfloat162*)(smem + OFF_B + n * B_STRIDE + k2 * 4) =
            __floats2bfloat162_rn(v.x, v.y);
    }
    // ---- stage first tile (buf 0) ----
    int cur = blockIdx.x;
    {
        const int n0 = cur * TILE_P;
        const float* fp = feats + (size_t)(n0 / HW) * CD * HW + (n0 % HW);
        for (int i = tid; i < 256 * 32; i += 512) {
            int row = i >> 5, p2 = i & 31;
            float2 v = *(const float2*)(fp + (size_t)row * HW + p2 * 2);
            *(__nv_bfloat162*)(smem + OFF_A + row * A_STRIDE + p2 * 4) =
                __floats2bfloat162_rn(v.x, v.y);
        }
        const int* lp = labels + (size_t)n0 * 256;
        for (int s = tid; s < 2048; s += 512) {
            int px = s >> 5, sub = s & 31;
            const int4* l4 = (const int4*)(lp + px * 256 + sub * 8);
            ((unsigned char*)(smem + OFF_LAB))[px * 32 + sub] =
                (unsigned char)mask8(l4[0], l4[1]);
        }
    }
    if (tid == 0) s_next[0] = atomicAdd(&g_counter, 1u);
    __syncthreads();

    // ldsm lane decomposition
    const int r8   = lane & 7;
    const int sel8 = (lane >> 3) & 1;
    const int selk = (lane >> 4) & 1;
    const uint32_t b_base = sb + OFF_B
        + (uint32_t)(wn * 64 + sel8 * 8 + r8) * B_STRIDE + (uint32_t)(selk * 8) * 2;
    const uint32_t a_lane_off =
        (uint32_t)(selk * 8 + r8) * A_STRIDE + (uint32_t)(wm * 16 + sel8 * 8) * 2;

    int p = 0;  // buffer parity
#pragma unroll 1
    while (true) {
        const int nxt = (int)s_next[p];
        const bool pf = nxt < NTILES;
        const uint32_t a_base = sb + OFF_A + (uint32_t)p * A_BUF + a_lane_off;
        char* anxt = smem + OFF_A + (p ^ 1) * A_BUF;
        unsigned char* lmnxt = (unsigned char*)(smem + OFF_LAB + (p ^ 1) * 2048);
        const float* fnx = nullptr; const int* lnx = nullptr;
        if (pf) {
            const int nn0 = nxt * TILE_P;
            fnx = feats + (size_t)(nn0 / HW) * CD * HW + (nn0 % HW);
            lnx = labels + (size_t)nn0 * 256;
        }

        float acc[8][4];
#pragma unroll
        for (int nb = 0; nb < 8; nb++)
#pragma unroll
            for (int e = 0; e < 4; e++) acc[nb][e] = 0.0f;

#pragma unroll
        for (int g = 0; g < 4; g++) {
            float4 pa0, pa1; int4 pl0, pl1;
            const int rowp = g * 64 + (tid >> 3);
            const int q = tid & 7;
            const int slot = g * 512 + tid, pxl = slot >> 5, sub = slot & 31;
            if (pf) {
                const float4* asrc = (const float4*)(fnx + (size_t)rowp * HW);
                pa0 = asrc[q]; pa1 = asrc[q + 8];
                const int4* lsrc = (const int4*)(lnx + pxl * 256 + sub * 8);
                pl0 = lsrc[0]; pl1 = lsrc[1];
            }
            // 4 ksteps of mma on tile cur
#pragma unroll
            for (int kk = 0; kk < 4; kk++) {
                const int ks = g * 4 + kk;
                uint32_t a[4], bq[4][4];
                ldsm_x4_t(a, a_base + (uint32_t)ks * 16 * A_STRIDE);
#pragma unroll
                for (int nbp = 0; nbp < 4; nbp++)
                    ldsm_x4(bq[nbp], b_base + (uint32_t)nbp * 16 * B_STRIDE + ks * 16 * 2);
#pragma unroll
                for (int nbp = 0; nbp < 4; nbp++) {
                    mma_bf16(acc[2 * nbp],     a, bq[nbp][0], bq[nbp][2]);
                    mma_bf16(acc[2 * nbp + 1], a, bq[nbp][1], bq[nbp][3]);
                }
            }
            // drain prefetch into nxt buffers
            if (pf) {
                __nv_bfloat162 lo0 = __floats2bfloat162_rn(pa0.x, pa0.y);
                __nv_bfloat162 hi0 = __floats2bfloat162_rn(pa0.z, pa0.w);
                uint2 v0 = { *(uint32_t*)&lo0, *(uint32_t*)&hi0 };
                *(uint2*)(anxt + rowp * A_STRIDE + q * 8) = v0;
                __nv_bfloat162 lo1 = __floats2bfloat162_rn(pa1.x, pa1.y);
                __nv_bfloat162 hi1 = __floats2bfloat162_rn(pa1.z, pa1.w);
                uint2 v1 = { *(uint32_t*)&lo1, *(uint32_t*)&hi1 };
                *(uint2*)(anxt + rowp * A_STRIDE + (q + 8) * 8) = v1;
                lmnxt[pxl * 32 + sub] = (unsigned char)mask8(pl0, pl1);
            }
        }
        if (tid == 0 && pf) s_next[p ^ 1] = atomicAdd(&g_counter, 1u);
        __syncthreads();   // nxt buffers + s_next[p^1] ready; acc final

        // ---- epilogue tile cur ----
        const unsigned* labm = (const unsigned*)(smem + OFF_LAB + p * 2048);
        float* s_en = (float*)(smem + OFF_RED);
        float* s_ep = s_en + 256;
#pragma unroll
        for (int half = 0; half < 2; half++) {
            const int row = wm * 16 + (lane >> 2) + half * 8;
            const unsigned mw0 = labm[row * 8 + wn * 2];
            const unsigned mw1 = labm[row * 8 + wn * 2 + 1];
            float en = 0.0f, ep = 0.0f;
#pragma unroll
            for (int nb = 0; nb < 8; nb++) {
                const unsigned mw = (nb < 4) ? mw0 : mw1;
                const int bit0 = (nb & 3) * 8 + (lane & 3) * 2;
                float l0 = acc[nb][half * 2]     * INV_T;
                float l1 = acc[nb][half * 2 + 1] * INV_T;
                bool y0 = (mw >> bit0) & 1u;
                bool y1 = (mw >> (bit0 + 1)) & 1u;
                float e0 = __expf(y0 ? -l0 : l0);
                float e1 = __expf(y1 ? -l1 : l1);
                en += y0 ? 0.0f : e0;  ep += y0 ? e0 : 0.0f;
                en += y1 ? 0.0f : e1;  ep += y1 ? e1 : 0.0f;
            }
            en += __shfl_xor_sync(0xffffffffu, en, 1);
            en += __shfl_xor_sync(0xffffffffu, en, 2);
            ep += __shfl_xor_sync(0xffffffffu, ep, 1);
            ep += __shfl_xor_sync(0xffffffffu, ep, 2);
            if ((lane & 3) == 0) { s_en[row * 4 + wn] = en; s_ep[row * 4 + wn] = ep; }
        }
        __syncthreads();
        if (tid < 64) {   // warps 0,1: 32 pixels each
            float en = s_en[tid * 4] + s_en[tid * 4 + 1] + s_en[tid * 4 + 2] + s_en[tid * 4 + 3];
            float ep = s_ep[tid * 4] + s_ep[tid * 4 + 1] + s_ep[tid * 4 + 2] + s_ep[tid * 4 + 3];
            float loss = __logf(en * ep + 1.0f);
            int   cnt  = (loss != 0.0f) ? 1 : 0;
#pragma unroll
            for (int off = 16; off > 0; off >>= 1) {
                loss += __shfl_xor_sync(0xffffffffu, loss, off);
                cnt  += __shfl_xor_sync(0xffffffffu, cnt,  off);
            }
            if (lane == 0) {   // deterministic per-tile slots
                g_partial[cur * 2 + wid] = loss;
                g_pcnt[cur * 2 + wid]    = cnt;
            }
        }
        if (!pf) break;
        cur = nxt;
        p ^= 1;
        // NOTE: s_en reads above are by warps 0,1 only; their next writes to s_en
        // occur after the next iteration's post-mma __syncthreads, which orders them.
    }
}

// ===================== finalize =====================
__global__ void __launch_bounds__(256) pcl_finalize(float* __restrict__ out)
{
    __shared__ float ss[256];
    __shared__ int   sc[256];
    float s = 0.0f; int c = 0;
    for (int i = threadIdx.x; i < NTILES * 2; i += 256) { s += g_partial[i]; c += g_pcnt[i]; }
    ss[threadIdx.x] = s; sc[threadIdx.x] = c;
    __syncthreads();
    for (int off = 128; off > 0; off >>= 1) {
        if (threadIdx.x < off) {
            ss[threadIdx.x] += ss[threadIdx.x + off];
            sc[threadIdx.x] += sc[threadIdx.x + off];
        }
        __syncthreads();
    }
    if (threadIdx.x == 0) {
        int cnt = sc[0];
        out[0] = (cnt == 0) ? 0.0f : ss[0] / (float)(cnt < 1 ? 1 : cnt);
    }
}

extern "C" void kernel_launch(void* const* d_in, const int* in_sizes, int n_in,
                              void* d_out, int out_size)
{
    const float* feats  = (const float*)d_in[0];
    const float* queue  = (const float*)d_in[1];
    const int*   labels = (const int*)d_in[2];
    float* out = (float*)d_out;

    static bool attr_set = false;
    if (!attr_set) {
        cudaFuncSetAttribute(pcl_main,
                             cudaFuncAttributeMaxDynamicSharedMemorySize, SMEM_SZ);
        attr_set = true;
    }

    pcl_init<<<1, 1>>>();
    pcl_main<<<GRID, 512, SMEM_SZ>>>(feats, queue, labels);
    pcl_finalize<<<1, 256>>>(out);
}

// round 6
// speedup vs baseline: 12.4795x; 1.0412x over previous
#include <cuda_runtime.h>
#include <cuda_bf16.h>
#include <cstdint>

#define NPIX   262144
#define CD     256
#define HW     16384
#define TILE_P 64
#define NTILES (NPIX / TILE_P)      // 4096
#define GRID   148
#define INV_T  14.285714285714285f

// smem layout (bytes)
#define B_STRIDE 528                  // 132 words = 4 mod 32 banks: conflict-free ldsm
#define A_STRIDE 144                  // 36 words  = 4 mod 32 banks
#define A_BUF    (256 * A_STRIDE)     // 36864
#define OFF_B    0
#define OFF_A    (256 * B_STRIDE)     // 135168
#define OFF_LAB  (OFF_A + 2 * A_BUF)  // 208896 : 2 x (64 px * 32 bytes)
#define SMEM_SZ  (OFF_LAB + 2 * 2048) // 212992

#define FIN_BLKS 512

__device__ float g_en[NTILES * 256];     // [tile][wn][row]  4MB
__device__ float g_ep[NTILES * 256];     // 4MB
__device__ float g_partial[FIN_BLKS];
__device__ int   g_pcnt[FIN_BLKS];

__device__ __forceinline__ uint32_t smem_u32(const void* p) {
    uint32_t a;
    asm("{ .reg .u64 t; cvta.to.shared.u64 t, %1; cvt.u32.u64 %0, t; }" : "=r"(a) : "l"(p));
    return a;
}
__device__ __forceinline__ void ldsm_x4(uint32_t* r, uint32_t addr) {
    asm volatile("ldmatrix.sync.aligned.m8n8.x4.shared.b16 {%0,%1,%2,%3}, [%4];"
                 : "=r"(r[0]), "=r"(r[1]), "=r"(r[2]), "=r"(r[3]) : "r"(addr));
}
__device__ __forceinline__ void ldsm_x4_t(uint32_t* r, uint32_t addr) {
    asm volatile("ldmatrix.sync.aligned.m8n8.x4.trans.shared.b16 {%0,%1,%2,%3}, [%4];"
                 : "=r"(r[0]), "=r"(r[1]), "=r"(r[2]), "=r"(r[3]) : "r"(addr));
}
__device__ __forceinline__ void mma_bf16(float* d, const uint32_t* a,
                                         uint32_t b0, uint32_t b1) {
    asm volatile(
        "mma.sync.aligned.m16n8k16.row.col.f32.bf16.bf16.f32 "
        "{%0,%1,%2,%3}, {%4,%5,%6,%7}, {%8,%9}, {%0,%1,%2,%3};"
        : "+f"(d[0]), "+f"(d[1]), "+f"(d[2]), "+f"(d[3])
        : "r"(a[0]), "r"(a[1]), "r"(a[2]), "r"(a[3]), "r"(b0), "r"(b1));
}
__device__ __forceinline__ unsigned mask8(const int4& v0, const int4& v1) {
    unsigned m = 0;
    m |= (v0.x != 0 ? 1u : 0u);
    m |= (v0.y != 0 ? 2u : 0u);
    m |= (v0.z != 0 ? 4u : 0u);
    m |= (v0.w != 0 ? 8u : 0u);
    m |= (v1.x != 0 ? 16u : 0u);
    m |= (v1.y != 0 ? 32u : 0u);
    m |= (v1.z != 0 ? 64u : 0u);
    m |= (v1.w != 0 ? 128u : 0u);
    return m;
}

// ===================== persistent fused main kernel =====================
// 148 CTAs x 512 thr (16 warps: wm 0..3 x wn 0..3). Static schedule over 4096
// tiles of 64 px; one __syncthreads per tile (A/label double-buffer flip).
__global__ void __launch_bounds__(512, 1)
pcl_main(const float* __restrict__ feats, const float* __restrict__ queue,
         const int* __restrict__ labels)
{
    extern __shared__ char smem[];
    const uint32_t sb = smem_u32(smem);
    const int tid = threadIdx.x, lane = tid & 31, wid = tid >> 5;
    const int wm = wid >> 2, wn = wid & 3;
    const int bid = blockIdx.x;

    // ---- stage B once: queue fp32 -> bf16 [n][k] ----
    for (int i = tid; i < 256 * 128; i += 512) {
        int n = i >> 7, k2 = i & 127;
        float2 v = *(const float2*)(queue + n * 256 + k2 * 2);
        *(__nv_bfloat162*)(smem + OFF_B + n * B_STRIDE + k2 * 4) =
            __floats2bfloat162_rn(v.x, v.y);
    }
    // ---- stage first tile (buf 0) ----
    {
        const int n0 = bid * TILE_P;
        const float* fp = feats + (size_t)(n0 / HW) * CD * HW + (n0 % HW);
        for (int i = tid; i < 256 * 32; i += 512) {
            int row = i >> 5, p2 = i & 31;
            float2 v = *(const float2*)(fp + (size_t)row * HW + p2 * 2);
            *(__nv_bfloat162*)(smem + OFF_A + row * A_STRIDE + p2 * 4) =
                __floats2bfloat162_rn(v.x, v.y);
        }
        const int* lp = labels + (size_t)n0 * 256;
        for (int s = tid; s < 2048; s += 512) {
            int px = s >> 5, sub = s & 31;
            const int4* l4 = (const int4*)(lp + px * 256 + sub * 8);
            ((unsigned char*)(smem + OFF_LAB))[px * 32 + sub] =
                (unsigned char)mask8(l4[0], l4[1]);
        }
    }
    __syncthreads();

    // ldsm lane decomposition
    const int r8   = lane & 7;
    const int sel8 = (lane >> 3) & 1;
    const int selk = (lane >> 4) & 1;
    const uint32_t b_base = sb + OFF_B
        + (uint32_t)(wn * 64 + sel8 * 8 + r8) * B_STRIDE + (uint32_t)(selk * 8) * 2;
    const uint32_t a_lane_off =
        (uint32_t)(selk * 8 + r8) * A_STRIDE + (uint32_t)(wm * 16 + sel8 * 8) * 2;

    int p = 0;  // buffer parity
#pragma unroll 1
    for (int cur = bid; cur < NTILES; cur += GRID, p ^= 1) {
        const int nxt = cur + GRID;
        const bool pf = nxt < NTILES;
        const uint32_t a_base = sb + OFF_A + (uint32_t)p * A_BUF + a_lane_off;
        char* anxt = smem + OFF_A + (p ^ 1) * A_BUF;
        unsigned char* lmnxt = (unsigned char*)(smem + OFF_LAB + (p ^ 1) * 2048);
        const float* fnx = nullptr; const int* lnx = nullptr;
        if (pf) {
            const int nn0 = nxt * TILE_P;
            fnx = feats + (size_t)(nn0 / HW) * CD * HW + (nn0 % HW);
            lnx = labels + (size_t)nn0 * 256;
        }

        float acc[8][4];
#pragma unroll
        for (int nb = 0; nb < 8; nb++)
#pragma unroll
            for (int e = 0; e < 4; e++) acc[nb][e] = 0.0f;

#pragma unroll
        for (int g = 0; g < 4; g++) {
            float4 pa0, pa1; int4 pl0, pl1;
            const int rowp = g * 64 + (tid >> 3);
            const int q = tid & 7;
            const int slot = g * 512 + tid, pxl = slot >> 5, sub = slot & 31;
            if (pf) {
                const float4* asrc = (const float4*)(fnx + (size_t)rowp * HW);
                pa0 = asrc[q]; pa1 = asrc[q + 8];
                const int4* lsrc = (const int4*)(lnx + pxl * 256 + sub * 8);
                pl0 = lsrc[0]; pl1 = lsrc[1];
            }
            // 4 ksteps of mma on tile cur
#pragma unroll
            for (int kk = 0; kk < 4; kk++) {
                const int ks = g * 4 + kk;
                uint32_t a[4], bq[4][4];
                ldsm_x4_t(a, a_base + (uint32_t)ks * 16 * A_STRIDE);
#pragma unroll
                for (int nbp = 0; nbp < 4; nbp++)
                    ldsm_x4(bq[nbp], b_base + (uint32_t)nbp * 16 * B_STRIDE + ks * 16 * 2);
#pragma unroll
                for (int nbp = 0; nbp < 4; nbp++) {
                    mma_bf16(acc[2 * nbp],     a, bq[nbp][0], bq[nbp][2]);
                    mma_bf16(acc[2 * nbp + 1], a, bq[nbp][1], bq[nbp][3]);
                }
            }
            // drain prefetch into nxt buffers
            if (pf) {
                __nv_bfloat162 lo0 = __floats2bfloat162_rn(pa0.x, pa0.y);
                __nv_bfloat162 hi0 = __floats2bfloat162_rn(pa0.z, pa0.w);
                uint2 v0 = { *(uint32_t*)&lo0, *(uint32_t*)&hi0 };
                *(uint2*)(anxt + rowp * A_STRIDE + q * 8) = v0;
                __nv_bfloat162 lo1 = __floats2bfloat162_rn(pa1.x, pa1.y);
                __nv_bfloat162 hi1 = __floats2bfloat162_rn(pa1.z, pa1.w);
                uint2 v1 = { *(uint32_t*)&lo1, *(uint32_t*)&hi1 };
                *(uint2*)(anxt + rowp * A_STRIDE + (q + 8) * 8) = v1;
                lmnxt[pxl * 32 + sub] = (unsigned char)mask8(pl0, pl1);
            }
        }

        // ---- epilogue tile cur: warp-local, no smem, no barrier ----
        const unsigned* labm = (const unsigned*)(smem + OFF_LAB + p * 2048);
#pragma unroll
        for (int half = 0; half < 2; half++) {
            const int row = wm * 16 + (lane >> 2) + half * 8;
            const unsigned mw0 = labm[row * 8 + wn * 2];
            const unsigned mw1 = labm[row * 8 + wn * 2 + 1];
            float en = 0.0f, ep = 0.0f;
#pragma unroll
            for (int nb = 0; nb < 8; nb++) {
                const unsigned mw = (nb < 4) ? mw0 : mw1;
                const int bit0 = (nb & 3) * 8 + (lane & 3) * 2;
                float l0 = acc[nb][half * 2]     * INV_T;
                float l1 = acc[nb][half * 2 + 1] * INV_T;
                bool y0 = (mw >> bit0) & 1u;
                bool y1 = (mw >> (bit0 + 1)) & 1u;
                float e0 = __expf(y0 ? -l0 : l0);
                float e1 = __expf(y1 ? -l1 : l1);
                en += y0 ? 0.0f : e0;  ep += y0 ? e0 : 0.0f;
                en += y1 ? 0.0f : e1;  ep += y1 ? e1 : 0.0f;
            }
            en += __shfl_xor_sync(0xffffffffu, en, 1);
            en += __shfl_xor_sync(0xffffffffu, en, 2);
            ep += __shfl_xor_sync(0xffffffffu, ep, 1);
            ep += __shfl_xor_sync(0xffffffffu, ep, 2);
            if ((lane & 3) == 0) {   // deterministic per-(tile,wn,row) slots
                const int slot = (cur * 4 + wn) * 64 + row;
                g_en[slot] = en;
                g_ep[slot] = ep;
            }
        }
        __syncthreads();   // flip double buffers
    }
}

// ===================== finalize 1: combine wn partials, per-block reduce =====
__global__ void __launch_bounds__(512) pcl_fin1()
{
    __shared__ float ss[16];
    __shared__ int   sc[16];
    const int n = blockIdx.x * 512 + threadIdx.x;   // pixel id
    const int tile = n >> 6, row = n & 63;
    const int base = tile * 256 + row;
    float en = g_en[base] + g_en[base + 64] + g_en[base + 128] + g_en[base + 192];
    float ep = g_ep[base] + g_ep[base + 64] + g_ep[base + 128] + g_ep[base + 192];
    float loss = __logf(en * ep + 1.0f);
    int   cnt  = (loss != 0.0f) ? 1 : 0;
#pragma unroll
    for (int off = 16; off > 0; off >>= 1) {
        loss += __shfl_xor_sync(0xffffffffu, loss, off);
        cnt  += __shfl_xor_sync(0xffffffffu, cnt,  off);
    }
    const int lane = threadIdx.x & 31, wid = threadIdx.x >> 5;
    if (lane == 0) { ss[wid] = loss; sc[wid] = cnt; }
    __syncthreads();
    if (threadIdx.x == 0) {
        float s = 0.0f; int c = 0;
#pragma unroll
        for (int w = 0; w < 16; w++) { s += ss[w]; c += sc[w]; }
        g_partial[blockIdx.x] = s;
        g_pcnt[blockIdx.x]    = c;
    }
}

// ===================== finalize 2: scalar =====================
__global__ void __launch_bounds__(512) pcl_fin2(float* __restrict__ out)
{
    __shared__ float ss[16];
    __shared__ int   sc[16];
    float s = g_partial[threadIdx.x];
    int   c = g_pcnt[threadIdx.x];
#pragma unroll
    for (int off = 16; off > 0; off >>= 1) {
        s += __shfl_xor_sync(0xffffffffu, s, off);
        c += __shfl_xor_sync(0xffffffffu, c, off);
    }
    const int lane = threadIdx.x & 31, wid = threadIdx.x >> 5;
    if (lane == 0) { ss[wid] = s; sc[wid] = c; }
    __syncthreads();
    if (threadIdx.x == 0) {
        float t = 0.0f; int c2 = 0;
#pragma unroll
        for (int w = 0; w < 16; w++) { t += ss[w]; c2 += sc[w]; }
        out[0] = (c2 == 0) ? 0.0f : t / (float)(c2 < 1 ? 1 : c2);
    }
}

extern "C" void kernel_launch(void* const* d_in, const int* in_sizes, int n_in,
                              void* d_out, int out_size)
{
    const float* feats  = (const float*)d_in[0];
    const float* queue  = (const float*)d_in[1];
    const int*   labels = (const int*)d_in[2];
    float* out = (float*)d_out;

    static bool attr_set = false;
    if (!attr_set) {
        cudaFuncSetAttribute(pcl_main,
                             cudaFuncAttributeMaxDynamicSharedMemorySize, SMEM_SZ);
        attr_set = true;
    }

    pcl_main<<<GRID, 512, SMEM_SZ>>>(feats, queue, labels);
    pcl_fin1<<<FIN_BLKS, 512>>>();
    pcl_fin2<<<1, 512>>>(out);
}